// round 2
// baseline (speedup 1.0000x reference)
#include <cuda_runtime.h>
#include <math.h>
#include <stdint.h>

// Problem constants
#define L_SEQ   2048
#define D_MODEL 2048
#define QKV_DIM 3072   // (16 + 2*4) * 128
#define NQH     16
#define NKVH    4
#define HD      128
#define WINDOW  1024

// Scratch (static device allocations; no cudaMalloc allowed)
__device__ float g_proj[L_SEQ * QKV_DIM];   // (L, 3072): q | k | v
__device__ float g_attn[L_SEQ * D_MODEL];   // (L, 2048): attention output

// ---------------------------------------------------------------------------
// SGEMM: C(MxN) = A(MxK) * B(KxN), row-major, fp32.
// 128x128 block tile, BK=16, 256 threads, 8x8 microtile per thread.
// M, N multiples of 128; K multiple of 16 (true for all our shapes).
// ---------------------------------------------------------------------------
__global__ __launch_bounds__(256) void sgemm_kernel(
    const float* __restrict__ A, const float* __restrict__ B,
    float* __restrict__ C, int M, int N, int K)
{
    __shared__ float As[16][132];  // transposed A tile, padded
    __shared__ float Bs[16][128];

    const int tid = threadIdx.x;
    const int bm = blockIdx.y * 128;
    const int bn = blockIdx.x * 128;
    const int tr = (tid >> 4) * 8;   // row offset of microtile
    const int tc = (tid & 15) * 8;   // col offset of microtile

    // load mappings
    const int arow = tid >> 2;          // 0..63 (and +64)
    const int acol = (tid & 3) * 4;     // 0,4,8,12
    const int brow = tid >> 5;          // 0..7 (and +8)
    const int bcol = (tid & 31) * 4;

    float acc[8][8];
#pragma unroll
    for (int i = 0; i < 8; i++)
#pragma unroll
        for (int j = 0; j < 8; j++) acc[i][j] = 0.0f;

    for (int k0 = 0; k0 < K; k0 += 16) {
        float4 a0 = *(const float4*)(A + (size_t)(bm + arow) * K + k0 + acol);
        float4 a1 = *(const float4*)(A + (size_t)(bm + arow + 64) * K + k0 + acol);
        float4 b0 = *(const float4*)(B + (size_t)(k0 + brow) * N + bn + bcol);
        float4 b1 = *(const float4*)(B + (size_t)(k0 + brow + 8) * N + bn + bcol);

        As[acol + 0][arow] = a0.x;
        As[acol + 1][arow] = a0.y;
        As[acol + 2][arow] = a0.z;
        As[acol + 3][arow] = a0.w;
        As[acol + 0][arow + 64] = a1.x;
        As[acol + 1][arow + 64] = a1.y;
        As[acol + 2][arow + 64] = a1.z;
        As[acol + 3][arow + 64] = a1.w;
        *(float4*)&Bs[brow][bcol] = b0;
        *(float4*)&Bs[brow + 8][bcol] = b1;
        __syncthreads();

#pragma unroll
        for (int kk = 0; kk < 16; kk++) {
            float a_[8], b_[8];
            *(float4*)&a_[0] = *(const float4*)&As[kk][tr];
            *(float4*)&a_[4] = *(const float4*)&As[kk][tr + 4];
            *(float4*)&b_[0] = *(const float4*)&Bs[kk][tc];
            *(float4*)&b_[4] = *(const float4*)&Bs[kk][tc + 4];
#pragma unroll
            for (int i = 0; i < 8; i++)
#pragma unroll
                for (int j = 0; j < 8; j++)
                    acc[i][j] += a_[i] * b_[j];
        }
        __syncthreads();
    }

#pragma unroll
    for (int i = 0; i < 8; i++) {
        float4 v0 = make_float4(acc[i][0], acc[i][1], acc[i][2], acc[i][3]);
        float4 v1 = make_float4(acc[i][4], acc[i][5], acc[i][6], acc[i][7]);
        *(float4*)(C + (size_t)(bm + tr + i) * N + bn + tc) = v0;
        *(float4*)(C + (size_t)(bm + tr + i) * N + bn + tc + 4) = v1;
    }
}

// ---------------------------------------------------------------------------
// RoPE (half-truncate): applied in-place to q (heads 0..15) and k (heads 16..19
// == cols 2048..2559) inside g_proj. dim/4 = 32 geometric freqs, 32 zero freqs.
// rotate: out1 = x1*cos + x2*sin ; out2 = -x1*sin + x2*cos
// grid = (L, 20), block = 64
// ---------------------------------------------------------------------------
__global__ void rope_kernel(float* __restrict__ proj)
{
    const int p = blockIdx.x;
    const int h = blockIdx.y;         // 0..19 -> col offset h*128 (q then k)
    const int j = threadIdx.x;        // 0..63

    float* row = proj + (size_t)p * QKV_DIM + h * HD;
    float x1 = row[j];
    float x2 = row[j + 64];
    float c = 1.0f, s = 0.0f;
    if (j < 32) {
        // freq = (1/1024)^(j/31) = 2^(-10*j/31)
        float f = exp2f(-10.0f * (float)j * (1.0f / 31.0f));
        float theta = (float)p * f;
        c = cosf(theta);
        s = sinf(theta);
    }
    row[j]      = x1 * c + x2 * s;
    row[j + 64] = -x1 * s + x2 * c;
}

// ---------------------------------------------------------------------------
// Fused attention with inverted mask + sink.
// Allowed(k | q)  =  (k > q) || (k + WINDOW <= q)      [reference puts -inf
// where causal&window holds, so we keep the complement]
// Sink: softmax over [logits, s[head]]; implemented by initializing the online
// softmax state with m = s, l = 1, O = 0.
//
// grid = (L/64, 16), block = 256 threads.
// Thread (ty,tx): ty=tid/16 owns rows r0=4*ty..+3; tx=tid%16:
//   - S phase: cols c0 = 4*tx..+3  (S is 64x64)
//   - O phase: cols oc0 = 8*tx..+7 (O is 64x128)
// ---------------------------------------------------------------------------
#define AT_BQ 64
#define AT_BK 64
#define KT_STRIDE 68   // padded, multiple of 4 for float4 alignment
#define PS_STRIDE 68

__global__ __launch_bounds__(256) void attn_kernel(
    const float* __restrict__ proj, const float* __restrict__ sink,
    float* __restrict__ out)
{
    extern __shared__ float sm[];
    float* Qs = sm;                          // 64 x 128
    float* Kt = Qs + 64 * 128;               // 128 x KT_STRIDE (transposed K)
    float* Vs = Kt + 128 * KT_STRIDE;        // 64 x 128
    float* Ps = Vs + 64 * 128;               // 64 x PS_STRIDE

    const int tid = threadIdx.x;
    const int hq = blockIdx.y;               // 0..15
    const int hk = hq >> 2;
    const int q0 = blockIdx.x * AT_BQ;
    const int ty = tid >> 4, tx = tid & 15;
    const int r0 = ty * 4;
    const int c0 = tx * 4;
    const int oc0 = tx * 8;

    const int qoff = hq * HD;
    const int koff = NQH * HD + hk * HD;              // 2048 + hk*128
    const int voff = (NQH + NKVH) * HD + hk * HD;     // 2560 + hk*128

    // Load Q tile (64 x 128)
    for (int n = tid; n < 64 * 32; n += 256) {
        int r = n >> 5, dv = n & 31;
        *(float4*)(Qs + r * 128 + dv * 4) =
            *(const float4*)(proj + (size_t)(q0 + r) * QKV_DIM + qoff + dv * 4);
    }

    float m[4], l[4], O[4][8];
    const float sval = sink[hq];
#pragma unroll
    for (int i = 0; i < 4; i++) {
        m[i] = sval;
        l[i] = 1.0f;
#pragma unroll
        for (int j = 0; j < 8; j++) O[i][j] = 0.0f;
    }
    __syncthreads();

    const float scale = 0.08838834764831845f;  // 1/sqrt(128)
    const float NEG_INF = -__int_as_float(0x7f800000);

    for (int k0 = 0; k0 < L_SEQ; k0 += AT_BK) {
        // Skip tiles where no (q,k) pair is allowed:
        // no future: k0+63 <= q0 ; no far-past: k0 > q0+63-1024
        if ((k0 + AT_BK - 1 <= q0) && (k0 > q0 + AT_BQ - 1 - WINDOW)) continue;

        // Load K tile transposed: Kt[d][k]
        for (int n = tid; n < 2048; n += 256) {
            int k = (n & 7) + ((n >> 8) << 3);
            int dv = (n >> 3) & 31;
            float4 v = *(const float4*)(proj + (size_t)(k0 + k) * QKV_DIM + koff + dv * 4);
            Kt[(dv * 4 + 0) * KT_STRIDE + k] = v.x;
            Kt[(dv * 4 + 1) * KT_STRIDE + k] = v.y;
            Kt[(dv * 4 + 2) * KT_STRIDE + k] = v.z;
            Kt[(dv * 4 + 3) * KT_STRIDE + k] = v.w;
        }
        // Load V tile natural: Vs[k][d]
        for (int n = tid; n < 2048; n += 256) {
            int k = n >> 5, dv = n & 31;
            *(float4*)(Vs + k * 128 + dv * 4) =
                *(const float4*)(proj + (size_t)(k0 + k) * QKV_DIM + voff + dv * 4);
        }
        __syncthreads();

        // S = Q * K^T (4x4 per thread)
        float acc[4][4];
#pragma unroll
        for (int i = 0; i < 4; i++)
#pragma unroll
            for (int j = 0; j < 4; j++) acc[i][j] = 0.0f;

#pragma unroll 8
        for (int dv = 0; dv < 32; dv++) {
            float qf[4][4], kf[4][4];
#pragma unroll
            for (int i = 0; i < 4; i++)
                *(float4*)qf[i] = *(const float4*)(Qs + (r0 + i) * 128 + dv * 4);
#pragma unroll
            for (int t = 0; t < 4; t++)
                *(float4*)kf[t] = *(const float4*)(Kt + (dv * 4 + t) * KT_STRIDE + c0);
#pragma unroll
            for (int i = 0; i < 4; i++)
#pragma unroll
                for (int j = 0; j < 4; j++)
                    acc[i][j] += qf[i][0] * kf[0][j] + qf[i][1] * kf[1][j] +
                                 qf[i][2] * kf[2][j] + qf[i][3] * kf[3][j];
        }

        // Mask + online softmax update per row
#pragma unroll
        for (int i = 0; i < 4; i++) {
            const int qp = q0 + r0 + i;
            float sc[4];
            float rowmax = NEG_INF;
#pragma unroll
            for (int j = 0; j < 4; j++) {
                int kp = k0 + c0 + j;
                bool allowed = (kp > qp) || (kp + WINDOW <= qp);
                sc[j] = allowed ? acc[i][j] * scale : NEG_INF;
                rowmax = fmaxf(rowmax, sc[j]);
            }
#pragma unroll
            for (int o = 8; o > 0; o >>= 1)
                rowmax = fmaxf(rowmax, __shfl_xor_sync(0xffffffffu, rowmax, o));

            float mn = fmaxf(m[i], rowmax);
            float alpha = __expf(m[i] - mn);
            float rs = 0.0f;
#pragma unroll
            for (int j = 0; j < 4; j++) {
                float p = __expf(sc[j] - mn);   // -inf -> 0
                rs += p;
                Ps[(r0 + i) * PS_STRIDE + c0 + j] = p;
            }
#pragma unroll
            for (int o = 8; o > 0; o >>= 1)
                rs += __shfl_xor_sync(0xffffffffu, rs, o);

            l[i] = l[i] * alpha + rs;
            m[i] = mn;
#pragma unroll
            for (int j = 0; j < 8; j++) O[i][j] *= alpha;
        }
        __syncthreads();

        // O += P * V (4 rows x 8 cols per thread)
#pragma unroll 4
        for (int kk4 = 0; kk4 < 16; kk4++) {
            float p_[4][4];
#pragma unroll
            for (int i = 0; i < 4; i++)
                *(float4*)p_[i] = *(const float4*)(Ps + (r0 + i) * PS_STRIDE + kk4 * 4);
#pragma unroll
            for (int t = 0; t < 4; t++) {
                const int kk = kk4 * 4 + t;
                float v0[4], v1[4];
                *(float4*)v0 = *(const float4*)(Vs + kk * 128 + oc0);
                *(float4*)v1 = *(const float4*)(Vs + kk * 128 + oc0 + 4);
#pragma unroll
                for (int i = 0; i < 4; i++) {
#pragma unroll
                    for (int j = 0; j < 4; j++) {
                        O[i][j]     += p_[i][t] * v0[j];
                        O[i][4 + j] += p_[i][t] * v1[j];
                    }
                }
            }
        }
        __syncthreads();
    }

    // Epilogue: normalize and store
#pragma unroll
    for (int i = 0; i < 4; i++) {
        float inv = 1.0f / l[i];
        float4 v0 = make_float4(O[i][0] * inv, O[i][1] * inv, O[i][2] * inv, O[i][3] * inv);
        float4 v1 = make_float4(O[i][4] * inv, O[i][5] * inv, O[i][6] * inv, O[i][7] * inv);
        float* dst = out + (size_t)(q0 + r0 + i) * D_MODEL + hq * HD + oc0;
        *(float4*)dst = v0;
        *(float4*)(dst + 4) = v1;
    }
}

// ---------------------------------------------------------------------------
// Launch
// ---------------------------------------------------------------------------
extern "C" void kernel_launch(void* const* d_in, const int* in_sizes, int n_in,
                              void* d_out, int out_size)
{
    const float* x    = (const float*)d_in[0];  // (1, 2048, 2048)
    const float* Wqkv = (const float*)d_in[1];  // (2048, 3072)
    const float* Wo   = (const float*)d_in[2];  // (2048, 2048)
    const float* s    = (const float*)d_in[3];  // (1, 16)
    float* out = (float*)d_out;                 // (1, 2048, 2048)

    float* proj = nullptr;
    float* attn = nullptr;
    cudaGetSymbolAddress((void**)&proj, g_proj);
    cudaGetSymbolAddress((void**)&attn, g_attn);

    // 1) QKV projection: (2048x2048) @ (2048x3072)
    {
        dim3 grid(QKV_DIM / 128, L_SEQ / 128);
        sgemm_kernel<<<grid, 256>>>(x, Wqkv, proj, L_SEQ, QKV_DIM, D_MODEL);
    }

    // 2) RoPE on q + k
    {
        dim3 grid(L_SEQ, NQH + NKVH);
        rope_kernel<<<grid, 64>>>(proj);
    }

    // 3) Fused attention
    {
        size_t smem = (size_t)(64 * 128 + 128 * KT_STRIDE + 64 * 128 + 64 * PS_STRIDE) * sizeof(float);
        cudaFuncSetAttribute(attn_kernel, cudaFuncAttributeMaxDynamicSharedMemorySize, (int)smem);
        dim3 grid(L_SEQ / AT_BQ, NQH);
        attn_kernel<<<grid, 256, smem>>>(proj, s, attn);
    }

    // 4) Output projection: (2048x2048) @ (2048x2048)
    {
        dim3 grid(D_MODEL / 128, L_SEQ / 128);
        sgemm_kernel<<<grid, 256>>>(attn, Wo, out, L_SEQ, D_MODEL, D_MODEL);
    }
}

// round 3
// speedup vs baseline: 1.5304x; 1.5304x over previous
#include <cuda_runtime.h>
#include <math.h>
#include <stdint.h>

// Problem constants
#define L_SEQ   2048
#define D_MODEL 2048
#define QKV_DIM 3072   // (16 + 2*4) * 128
#define NQH     16
#define NKVH    4
#define HD      128
#define WINDOW  1024

// Scratch (static device allocations; no cudaMalloc allowed)
__device__ float g_proj[L_SEQ * QKV_DIM];   // (L, 3072): q | k | v
__device__ float g_attn[L_SEQ * D_MODEL];   // (L, 2048): attention output

// ---------------------------------------------------------------------------
// tf32 helpers
// ---------------------------------------------------------------------------
__device__ __forceinline__ uint32_t f2tf32(float f) {
    uint32_t r;
    asm("cvt.rna.tf32.f32 %0, %1;" : "=r"(r) : "f"(f));
    return r;
}

__device__ __forceinline__ void mma_tf32(
    float& c0, float& c1, float& c2, float& c3,
    uint32_t a0, uint32_t a1, uint32_t a2, uint32_t a3,
    uint32_t b0, uint32_t b1)
{
    asm volatile(
        "mma.sync.aligned.m16n8k8.row.col.f32.tf32.tf32.f32 "
        "{%0,%1,%2,%3}, {%4,%5,%6,%7}, {%8,%9}, {%0,%1,%2,%3};\n"
        : "+f"(c0), "+f"(c1), "+f"(c2), "+f"(c3)
        : "r"(a0), "r"(a1), "r"(a2), "r"(a3), "r"(b0), "r"(b1));
}

// ---------------------------------------------------------------------------
// TF32 tensor-core GEMM: C(MxN) = A(MxK) * B(KxN), row-major fp32 in/out.
// 128x128 block tile, BK=32, 256 threads.
// Warp grid 2(M) x 4(N): warp tile 64x32 = 4 mtiles(16) x 4 ntiles(8).
// A smem [128][36] (m-major, padded), B smem [32][132], both tf32 bits.
// Global->smem path converts to tf32 once; register-staged prefetch.
// ---------------------------------------------------------------------------
#define GA_STR 36
#define GB_STR 132

__global__ __launch_bounds__(256) void mma_gemm_kernel(
    const float* __restrict__ A, const float* __restrict__ B,
    float* __restrict__ C, int M, int N, int K)
{
    __shared__ uint32_t As[128][GA_STR];
    __shared__ uint32_t Bs[32][GB_STR];

    const int tid = threadIdx.x;
    const int bm = blockIdx.y * 128;
    const int bn = blockIdx.x * 128;

    const int w = tid >> 5, lane = tid & 31;
    const int wm = (w >> 2) * 64;   // 0 or 64
    const int wn = (w & 3) * 32;    // 0,32,64,96
    const int grp = lane >> 2;      // 0..7
    const int qid = lane & 3;       // 0..3

    // load mappings
    const int arow = tid >> 3;          // 0..31  (A rows, +32*i)
    const int acol = (tid & 7) * 4;     // 0..28
    const int brow = tid >> 5;          // 0..7   (B rows, +8*i)
    const int bcol = (tid & 31) * 4;    // 0..124

    float acc[4][4][4];  // [mt][nt][c0..c3]
#pragma unroll
    for (int mt = 0; mt < 4; mt++)
#pragma unroll
        for (int nt = 0; nt < 4; nt++)
#pragma unroll
            for (int c = 0; c < 4; c++) acc[mt][nt][c] = 0.0f;

    float4 sa[4], sb[4];

    // Prologue: load first tile into registers
#pragma unroll
    for (int i = 0; i < 4; i++) {
        sa[i] = *(const float4*)(A + (size_t)(bm + arow + i * 32) * K + acol);
        sb[i] = *(const float4*)(B + (size_t)(brow + i * 8) * N + bn + bcol);
    }

    for (int k0 = 0; k0 < K; k0 += 32) {
        // Stage current tile regs -> smem (tf32 convert)
#pragma unroll
        for (int i = 0; i < 4; i++) {
            uint32_t* pa = &As[arow + i * 32][acol];
            pa[0] = f2tf32(sa[i].x); pa[1] = f2tf32(sa[i].y);
            pa[2] = f2tf32(sa[i].z); pa[3] = f2tf32(sa[i].w);
            uint32_t* pb = &Bs[brow + i * 8][bcol];
            pb[0] = f2tf32(sb[i].x); pb[1] = f2tf32(sb[i].y);
            pb[2] = f2tf32(sb[i].z); pb[3] = f2tf32(sb[i].w);
        }
        __syncthreads();

        // Prefetch next tile into registers (overlaps with MMA below)
        if (k0 + 32 < K) {
#pragma unroll
            for (int i = 0; i < 4; i++) {
                sa[i] = *(const float4*)(A + (size_t)(bm + arow + i * 32) * K + k0 + 32 + acol);
                sb[i] = *(const float4*)(B + (size_t)(k0 + 32 + brow + i * 8) * N + bn + bcol);
            }
        }

        // Compute: 4 k-steps of 8
#pragma unroll
        for (int ks = 0; ks < 4; ks++) {
            const int kk = ks * 8;
            uint32_t bf[4][2];
#pragma unroll
            for (int nt = 0; nt < 4; nt++) {
                bf[nt][0] = Bs[kk + qid][wn + nt * 8 + grp];
                bf[nt][1] = Bs[kk + qid + 4][wn + nt * 8 + grp];
            }
#pragma unroll
            for (int mt = 0; mt < 4; mt++) {
                const int r = wm + mt * 16 + grp;
                uint32_t a0 = As[r][kk + qid];
                uint32_t a1 = As[r + 8][kk + qid];
                uint32_t a2 = As[r][kk + qid + 4];
                uint32_t a3 = As[r + 8][kk + qid + 4];
#pragma unroll
                for (int nt = 0; nt < 4; nt++)
                    mma_tf32(acc[mt][nt][0], acc[mt][nt][1], acc[mt][nt][2], acc[mt][nt][3],
                             a0, a1, a2, a3, bf[nt][0], bf[nt][1]);
            }
        }
        __syncthreads();
    }

    // Epilogue: c0: (grp, qid*2), c1: +1 col, c2/c3: row+8
#pragma unroll
    for (int mt = 0; mt < 4; mt++) {
        const int r = bm + wm + mt * 16 + grp;
#pragma unroll
        for (int nt = 0; nt < 4; nt++) {
            const int cc = bn + wn + nt * 8 + qid * 2;
            *(float2*)(C + (size_t)r * N + cc) = make_float2(acc[mt][nt][0], acc[mt][nt][1]);
            *(float2*)(C + (size_t)(r + 8) * N + cc) = make_float2(acc[mt][nt][2], acc[mt][nt][3]);
        }
    }
}

// ---------------------------------------------------------------------------
// RoPE (half-truncate): q (heads 0..15) and k (heads 16..19) in-place.
// ---------------------------------------------------------------------------
__global__ void rope_kernel(float* __restrict__ proj)
{
    const int p = blockIdx.x;
    const int h = blockIdx.y;         // 0..19
    const int j = threadIdx.x;        // 0..63

    float* row = proj + (size_t)p * QKV_DIM + h * HD;
    float x1 = row[j];
    float x2 = row[j + 64];
    float c = 1.0f, s = 0.0f;
    if (j < 32) {
        float f = exp2f(-10.0f * (float)j * (1.0f / 31.0f));
        float theta = (float)p * f;
        c = cosf(theta);
        s = sinf(theta);
    }
    row[j]      = x1 * c + x2 * s;
    row[j + 64] = -x1 * s + x2 * c;
}

// ---------------------------------------------------------------------------
// Fused attention with inverted mask + sink (unchanged from R2).
// Allowed(k|q) = (k > q) || (k + WINDOW <= q)
// ---------------------------------------------------------------------------
#define AT_BQ 64
#define AT_BK 64
#define KT_STRIDE 68
#define PS_STRIDE 68

__global__ __launch_bounds__(256) void attn_kernel(
    const float* __restrict__ proj, const float* __restrict__ sink,
    float* __restrict__ out)
{
    extern __shared__ float sm[];
    float* Qs = sm;                          // 64 x 128
    float* Kt = Qs + 64 * 128;               // 128 x KT_STRIDE
    float* Vs = Kt + 128 * KT_STRIDE;        // 64 x 128
    float* Ps = Vs + 64 * 128;               // 64 x PS_STRIDE

    const int tid = threadIdx.x;
    const int hq = blockIdx.y;
    const int hk = hq >> 2;
    const int q0 = blockIdx.x * AT_BQ;
    const int ty = tid >> 4, tx = tid & 15;
    const int r0 = ty * 4;
    const int c0 = tx * 4;
    const int oc0 = tx * 8;

    const int qoff = hq * HD;
    const int koff = NQH * HD + hk * HD;
    const int voff = (NQH + NKVH) * HD + hk * HD;

    for (int n = tid; n < 64 * 32; n += 256) {
        int r = n >> 5, dv = n & 31;
        *(float4*)(Qs + r * 128 + dv * 4) =
            *(const float4*)(proj + (size_t)(q0 + r) * QKV_DIM + qoff + dv * 4);
    }

    float m[4], l[4], O[4][8];
    const float sval = sink[hq];
#pragma unroll
    for (int i = 0; i < 4; i++) {
        m[i] = sval;
        l[i] = 1.0f;
#pragma unroll
        for (int j = 0; j < 8; j++) O[i][j] = 0.0f;
    }
    __syncthreads();

    const float scale = 0.08838834764831845f;
    const float NEG_INF = -__int_as_float(0x7f800000);

    for (int k0 = 0; k0 < L_SEQ; k0 += AT_BK) {
        if ((k0 + AT_BK - 1 <= q0) && (k0 > q0 + AT_BQ - 1 - WINDOW)) continue;

        for (int n = tid; n < 2048; n += 256) {
            int k = (n & 7) + ((n >> 8) << 3);
            int dv = (n >> 3) & 31;
            float4 v = *(const float4*)(proj + (size_t)(k0 + k) * QKV_DIM + koff + dv * 4);
            Kt[(dv * 4 + 0) * KT_STRIDE + k] = v.x;
            Kt[(dv * 4 + 1) * KT_STRIDE + k] = v.y;
            Kt[(dv * 4 + 2) * KT_STRIDE + k] = v.z;
            Kt[(dv * 4 + 3) * KT_STRIDE + k] = v.w;
        }
        for (int n = tid; n < 2048; n += 256) {
            int k = n >> 5, dv = n & 31;
            *(float4*)(Vs + k * 128 + dv * 4) =
                *(const float4*)(proj + (size_t)(k0 + k) * QKV_DIM + voff + dv * 4);
        }
        __syncthreads();

        float acc[4][4];
#pragma unroll
        for (int i = 0; i < 4; i++)
#pragma unroll
            for (int j = 0; j < 4; j++) acc[i][j] = 0.0f;

#pragma unroll 8
        for (int dv = 0; dv < 32; dv++) {
            float qf[4][4], kf[4][4];
#pragma unroll
            for (int i = 0; i < 4; i++)
                *(float4*)qf[i] = *(const float4*)(Qs + (r0 + i) * 128 + dv * 4);
#pragma unroll
            for (int t = 0; t < 4; t++)
                *(float4*)kf[t] = *(const float4*)(Kt + (dv * 4 + t) * KT_STRIDE + c0);
#pragma unroll
            for (int i = 0; i < 4; i++)
#pragma unroll
                for (int j = 0; j < 4; j++)
                    acc[i][j] += qf[i][0] * kf[0][j] + qf[i][1] * kf[1][j] +
                                 qf[i][2] * kf[2][j] + qf[i][3] * kf[3][j];
        }

#pragma unroll
        for (int i = 0; i < 4; i++) {
            const int qp = q0 + r0 + i;
            float sc[4];
            float rowmax = NEG_INF;
#pragma unroll
            for (int j = 0; j < 4; j++) {
                int kp = k0 + c0 + j;
                bool allowed = (kp > qp) || (kp + WINDOW <= qp);
                sc[j] = allowed ? acc[i][j] * scale : NEG_INF;
                rowmax = fmaxf(rowmax, sc[j]);
            }
#pragma unroll
            for (int o = 8; o > 0; o >>= 1)
                rowmax = fmaxf(rowmax, __shfl_xor_sync(0xffffffffu, rowmax, o));

            float mn = fmaxf(m[i], rowmax);
            float alpha = __expf(m[i] - mn);
            float rs = 0.0f;
#pragma unroll
            for (int j = 0; j < 4; j++) {
                float p = __expf(sc[j] - mn);
                rs += p;
                Ps[(r0 + i) * PS_STRIDE + c0 + j] = p;
            }
#pragma unroll
            for (int o = 8; o > 0; o >>= 1)
                rs += __shfl_xor_sync(0xffffffffu, rs, o);

            l[i] = l[i] * alpha + rs;
            m[i] = mn;
#pragma unroll
            for (int j = 0; j < 8; j++) O[i][j] *= alpha;
        }
        __syncthreads();

#pragma unroll 4
        for (int kk4 = 0; kk4 < 16; kk4++) {
            float p_[4][4];
#pragma unroll
            for (int i = 0; i < 4; i++)
                *(float4*)p_[i] = *(const float4*)(Ps + (r0 + i) * PS_STRIDE + kk4 * 4);
#pragma unroll
            for (int t = 0; t < 4; t++) {
                const int kk = kk4 * 4 + t;
                float v0[4], v1[4];
                *(float4*)v0 = *(const float4*)(Vs + kk * 128 + oc0);
                *(float4*)v1 = *(const float4*)(Vs + kk * 128 + oc0 + 4);
#pragma unroll
                for (int i = 0; i < 4; i++) {
#pragma unroll
                    for (int j = 0; j < 4; j++) {
                        O[i][j]     += p_[i][t] * v0[j];
                        O[i][4 + j] += p_[i][t] * v1[j];
                    }
                }
            }
        }
        __syncthreads();
    }

#pragma unroll
    for (int i = 0; i < 4; i++) {
        float inv = 1.0f / l[i];
        float4 v0 = make_float4(O[i][0] * inv, O[i][1] * inv, O[i][2] * inv, O[i][3] * inv);
        float4 v1 = make_float4(O[i][4] * inv, O[i][5] * inv, O[i][6] * inv, O[i][7] * inv);
        float* dst = out + (size_t)(q0 + r0 + i) * D_MODEL + hq * HD + oc0;
        *(float4*)dst = v0;
        *(float4*)(dst + 4) = v1;
    }
}

// ---------------------------------------------------------------------------
// Launch
// ---------------------------------------------------------------------------
extern "C" void kernel_launch(void* const* d_in, const int* in_sizes, int n_in,
                              void* d_out, int out_size)
{
    const float* x    = (const float*)d_in[0];  // (1, 2048, 2048)
    const float* Wqkv = (const float*)d_in[1];  // (2048, 3072)
    const float* Wo   = (const float*)d_in[2];  // (2048, 2048)
    const float* s    = (const float*)d_in[3];  // (1, 16)
    float* out = (float*)d_out;                 // (1, 2048, 2048)

    float* proj = nullptr;
    float* attn = nullptr;
    cudaGetSymbolAddress((void**)&proj, g_proj);
    cudaGetSymbolAddress((void**)&attn, g_attn);

    // 1) QKV projection: (2048x2048) @ (2048x3072), tf32 tensor cores
    {
        dim3 grid(QKV_DIM / 128, L_SEQ / 128);
        mma_gemm_kernel<<<grid, 256>>>(x, Wqkv, proj, L_SEQ, QKV_DIM, D_MODEL);
    }

    // 2) RoPE on q + k
    {
        dim3 grid(L_SEQ, NQH + NKVH);
        rope_kernel<<<grid, 64>>>(proj);
    }

    // 3) Fused attention
    {
        size_t smem = (size_t)(64 * 128 + 128 * KT_STRIDE + 64 * 128 + 64 * PS_STRIDE) * sizeof(float);
        cudaFuncSetAttribute(attn_kernel, cudaFuncAttributeMaxDynamicSharedMemorySize, (int)smem);
        dim3 grid(L_SEQ / AT_BQ, NQH);
        attn_kernel<<<grid, 256, smem>>>(proj, s, attn);
    }

    // 4) Output projection: (2048x2048) @ (2048x2048), tf32 tensor cores
    {
        dim3 grid(D_MODEL / 128, L_SEQ / 128);
        mma_gemm_kernel<<<grid, 256>>>(attn, Wo, out, L_SEQ, D_MODEL, D_MODEL);
    }
}

// round 4
// speedup vs baseline: 3.1264x; 2.0429x over previous
#include <cuda_runtime.h>
#include <math.h>
#include <stdint.h>

// Problem constants
#define L_SEQ   2048
#define D_MODEL 2048
#define QKV_DIM 3072   // (16 + 2*4) * 128
#define NQH     16
#define NKVH    4
#define HD      128
#define WINDOW  1024

// Scratch (static device allocations; no cudaMalloc allowed)
__device__ float g_proj[L_SEQ * QKV_DIM];   // (L, 3072): q | k | v
__device__ float g_attn[L_SEQ * D_MODEL];   // (L, 2048): attention output

// ---------------------------------------------------------------------------
// tf32 helpers
// ---------------------------------------------------------------------------
__device__ __forceinline__ uint32_t f2tf32(float f) {
    uint32_t r;
    asm("cvt.rna.tf32.f32 %0, %1;" : "=r"(r) : "f"(f));
    return r;
}

__device__ __forceinline__ void mma_tf32(
    float& c0, float& c1, float& c2, float& c3,
    uint32_t a0, uint32_t a1, uint32_t a2, uint32_t a3,
    uint32_t b0, uint32_t b1)
{
    asm volatile(
        "mma.sync.aligned.m16n8k8.row.col.f32.tf32.tf32.f32 "
        "{%0,%1,%2,%3}, {%4,%5,%6,%7}, {%8,%9}, {%0,%1,%2,%3};\n"
        : "+f"(c0), "+f"(c1), "+f"(c2), "+f"(c3)
        : "r"(a0), "r"(a1), "r"(a2), "r"(a3), "r"(b0), "r"(b1));
}

// ---------------------------------------------------------------------------
// TF32 tensor-core GEMM (unchanged from R3): C = A * B, row-major fp32 io.
// ---------------------------------------------------------------------------
#define GA_STR 36
#define GB_STR 132

__global__ __launch_bounds__(256) void mma_gemm_kernel(
    const float* __restrict__ A, const float* __restrict__ B,
    float* __restrict__ C, int M, int N, int K)
{
    __shared__ uint32_t As[128][GA_STR];
    __shared__ uint32_t Bs[32][GB_STR];

    const int tid = threadIdx.x;
    const int bm = blockIdx.y * 128;
    const int bn = blockIdx.x * 128;

    const int w = tid >> 5, lane = tid & 31;
    const int wm = (w >> 2) * 64;
    const int wn = (w & 3) * 32;
    const int grp = lane >> 2;
    const int qid = lane & 3;

    const int arow = tid >> 3;
    const int acol = (tid & 7) * 4;
    const int brow = tid >> 5;
    const int bcol = (tid & 31) * 4;

    float acc[4][4][4];
#pragma unroll
    for (int mt = 0; mt < 4; mt++)
#pragma unroll
        for (int nt = 0; nt < 4; nt++)
#pragma unroll
            for (int c = 0; c < 4; c++) acc[mt][nt][c] = 0.0f;

    float4 sa[4], sb[4];
#pragma unroll
    for (int i = 0; i < 4; i++) {
        sa[i] = *(const float4*)(A + (size_t)(bm + arow + i * 32) * K + acol);
        sb[i] = *(const float4*)(B + (size_t)(brow + i * 8) * N + bn + bcol);
    }

    for (int k0 = 0; k0 < K; k0 += 32) {
#pragma unroll
        for (int i = 0; i < 4; i++) {
            uint32_t* pa = &As[arow + i * 32][acol];
            pa[0] = f2tf32(sa[i].x); pa[1] = f2tf32(sa[i].y);
            pa[2] = f2tf32(sa[i].z); pa[3] = f2tf32(sa[i].w);
            uint32_t* pb = &Bs[brow + i * 8][bcol];
            pb[0] = f2tf32(sb[i].x); pb[1] = f2tf32(sb[i].y);
            pb[2] = f2tf32(sb[i].z); pb[3] = f2tf32(sb[i].w);
        }
        __syncthreads();

        if (k0 + 32 < K) {
#pragma unroll
            for (int i = 0; i < 4; i++) {
                sa[i] = *(const float4*)(A + (size_t)(bm + arow + i * 32) * K + k0 + 32 + acol);
                sb[i] = *(const float4*)(B + (size_t)(k0 + 32 + brow + i * 8) * N + bn + bcol);
            }
        }

#pragma unroll
        for (int ks = 0; ks < 4; ks++) {
            const int kk = ks * 8;
            uint32_t bf[4][2];
#pragma unroll
            for (int nt = 0; nt < 4; nt++) {
                bf[nt][0] = Bs[kk + qid][wn + nt * 8 + grp];
                bf[nt][1] = Bs[kk + qid + 4][wn + nt * 8 + grp];
            }
#pragma unroll
            for (int mt = 0; mt < 4; mt++) {
                const int r = wm + mt * 16 + grp;
                uint32_t a0 = As[r][kk + qid];
                uint32_t a1 = As[r + 8][kk + qid];
                uint32_t a2 = As[r][kk + qid + 4];
                uint32_t a3 = As[r + 8][kk + qid + 4];
#pragma unroll
                for (int nt = 0; nt < 4; nt++)
                    mma_tf32(acc[mt][nt][0], acc[mt][nt][1], acc[mt][nt][2], acc[mt][nt][3],
                             a0, a1, a2, a3, bf[nt][0], bf[nt][1]);
            }
        }
        __syncthreads();
    }

#pragma unroll
    for (int mt = 0; mt < 4; mt++) {
        const int r = bm + wm + mt * 16 + grp;
#pragma unroll
        for (int nt = 0; nt < 4; nt++) {
            const int cc = bn + wn + nt * 8 + qid * 2;
            *(float2*)(C + (size_t)r * N + cc) = make_float2(acc[mt][nt][0], acc[mt][nt][1]);
            *(float2*)(C + (size_t)(r + 8) * N + cc) = make_float2(acc[mt][nt][2], acc[mt][nt][3]);
        }
    }
}

// ---------------------------------------------------------------------------
// RoPE (half-truncate), unchanged.
// ---------------------------------------------------------------------------
__global__ void rope_kernel(float* __restrict__ proj)
{
    const int p = blockIdx.x;
    const int h = blockIdx.y;
    const int j = threadIdx.x;

    float* row = proj + (size_t)p * QKV_DIM + h * HD;
    float x1 = row[j];
    float x2 = row[j + 64];
    float c = 1.0f, s = 0.0f;
    if (j < 32) {
        float f = exp2f(-10.0f * (float)j * (1.0f / 31.0f));
        float theta = (float)p * f;
        c = cosf(theta);
        s = sinf(theta);
    }
    row[j]      = x1 * c + x2 * s;
    row[j + 64] = -x1 * s + x2 * c;
}

// ---------------------------------------------------------------------------
// TF32 tensor-core flash attention with inverted mask + sink.
// Allowed(k|q) = (k > q) || (k + WINDOW <= q).
// Block: 128 threads (4 warps). Each warp owns a 16-row Q stripe; BQ=64, BK=64.
// S = Q K^T via m16n8k8 (K read natural row-major for the col-B fragment),
// softmax in c-fragments (rows grp/grp+8, quad shfl reductions),
// P -> smem (tf32, aliases the K buffer), O += P V via m16n8k8.
// smem: Qs[64][132] | KPs[64][132] (K, later P stride 68) | Vs[64][136] = 100KB.
// ---------------------------------------------------------------------------
#define AT_BQ 64
#define AT_BK 64
#define QS_STR 132
#define KS_STR 132
#define VS_STR 136
#define PS_STR 68

__global__ __launch_bounds__(128) void attn_mma_kernel(
    const float* __restrict__ proj, const float* __restrict__ sink,
    float* __restrict__ out)
{
    extern __shared__ uint32_t smu[];
    uint32_t* Qs  = smu;                         // 64 x QS_STR
    uint32_t* KPs = Qs + 64 * QS_STR;            // 64 x KS_STR (K; aliased as P)
    uint32_t* Vs  = KPs + 64 * KS_STR;           // 64 x VS_STR

    const int tid  = threadIdx.x;
    const int w    = tid >> 5;
    const int lane = tid & 31;
    const int grp  = lane >> 2;
    const int qid  = lane & 3;
    const int row0 = w * 16;                     // warp's q-row stripe

    const int hq = blockIdx.y;
    const int hk = hq >> 2;
    const int q0 = blockIdx.x * AT_BQ;

    const int qoff = hq * HD;
    const int koff = NQH * HD + hk * HD;
    const int voff = (NQH + NKVH) * HD + hk * HD;

    // Load Q tile (64 x 128) as tf32 bits
    for (int n = tid; n < 64 * 32; n += 128) {
        int r = n >> 5, dv = n & 31;
        float4 v = *(const float4*)(proj + (size_t)(q0 + r) * QKV_DIM + qoff + dv * 4);
        uint4 t = make_uint4(f2tf32(v.x), f2tf32(v.y), f2tf32(v.z), f2tf32(v.w));
        *(uint4*)(Qs + r * QS_STR + dv * 4) = t;
    }

    const float sval = sink[hq];
    float m0 = sval, m1 = sval, l0 = 1.0f, l1 = 1.0f;
    float O[16][4];
#pragma unroll
    for (int nt = 0; nt < 16; nt++)
#pragma unroll
        for (int c = 0; c < 4; c++) O[nt][c] = 0.0f;

    const float scale = 0.08838834764831845f;   // 1/sqrt(128)
    const float NEG_INF = -__int_as_float(0x7f800000);

    for (int k0 = 0; k0 < L_SEQ; k0 += AT_BK) {
        // Skip fully-disallowed tiles
        if ((k0 + AT_BK - 1 <= q0) && (k0 > q0 + AT_BQ - 1 - WINDOW)) continue;

        __syncthreads();   // prior tile's P/V reads complete before overwrite

        // Load K (64 x 128) and V (64 x 128) as tf32 bits
        for (int n = tid; n < 64 * 32; n += 128) {
            int r = n >> 5, dv = n & 31;
            float4 kv = *(const float4*)(proj + (size_t)(k0 + r) * QKV_DIM + koff + dv * 4);
            *(uint4*)(KPs + r * KS_STR + dv * 4) =
                make_uint4(f2tf32(kv.x), f2tf32(kv.y), f2tf32(kv.z), f2tf32(kv.w));
            float4 vv = *(const float4*)(proj + (size_t)(k0 + r) * QKV_DIM + voff + dv * 4);
            *(uint4*)(Vs + r * VS_STR + dv * 4) =
                make_uint4(f2tf32(vv.x), f2tf32(vv.y), f2tf32(vv.z), f2tf32(vv.w));
        }
        __syncthreads();

        // ---- S = Q K^T : m16 x n64 x k128 per warp ----
        float S[8][4];
#pragma unroll
        for (int nt = 0; nt < 8; nt++)
#pragma unroll
            for (int c = 0; c < 4; c++) S[nt][c] = 0.0f;

#pragma unroll
        for (int ks = 0; ks < 16; ks++) {
            const int kk = ks * 8;
            uint32_t a0 = Qs[(row0 + grp) * QS_STR + kk + qid];
            uint32_t a1 = Qs[(row0 + grp + 8) * QS_STR + kk + qid];
            uint32_t a2 = Qs[(row0 + grp) * QS_STR + kk + qid + 4];
            uint32_t a3 = Qs[(row0 + grp + 8) * QS_STR + kk + qid + 4];
#pragma unroll
            for (int nt = 0; nt < 8; nt++) {
                uint32_t b0 = KPs[(nt * 8 + grp) * KS_STR + kk + qid];
                uint32_t b1 = KPs[(nt * 8 + grp) * KS_STR + kk + qid + 4];
                mma_tf32(S[nt][0], S[nt][1], S[nt][2], S[nt][3], a0, a1, a2, a3, b0, b1);
            }
        }

        // ---- mask + scale + row maxima ----
        const int qp0 = q0 + row0 + grp;
        const int qp1 = qp0 + 8;
        const bool needs_mask = !((k0 > q0 + AT_BQ - 1) ||
                                  (k0 + AT_BK - 1 + WINDOW <= q0));
        float mx0 = NEG_INF, mx1 = NEG_INF;
#pragma unroll
        for (int nt = 0; nt < 8; nt++) {
            const int kpa = k0 + nt * 8 + 2 * qid;
            const int kpb = kpa + 1;
            if (needs_mask) {
                S[nt][0] = ((kpa > qp0) || (kpa + WINDOW <= qp0)) ? S[nt][0] * scale : NEG_INF;
                S[nt][1] = ((kpb > qp0) || (kpb + WINDOW <= qp0)) ? S[nt][1] * scale : NEG_INF;
                S[nt][2] = ((kpa > qp1) || (kpa + WINDOW <= qp1)) ? S[nt][2] * scale : NEG_INF;
                S[nt][3] = ((kpb > qp1) || (kpb + WINDOW <= qp1)) ? S[nt][3] * scale : NEG_INF;
            } else {
                S[nt][0] *= scale; S[nt][1] *= scale;
                S[nt][2] *= scale; S[nt][3] *= scale;
            }
            mx0 = fmaxf(mx0, fmaxf(S[nt][0], S[nt][1]));
            mx1 = fmaxf(mx1, fmaxf(S[nt][2], S[nt][3]));
        }
        mx0 = fmaxf(mx0, __shfl_xor_sync(0xffffffffu, mx0, 1));
        mx0 = fmaxf(mx0, __shfl_xor_sync(0xffffffffu, mx0, 2));
        mx1 = fmaxf(mx1, __shfl_xor_sync(0xffffffffu, mx1, 1));
        mx1 = fmaxf(mx1, __shfl_xor_sync(0xffffffffu, mx1, 2));

        const float mn0 = fmaxf(m0, mx0);
        const float mn1 = fmaxf(m1, mx1);
        const float alpha0 = __expf(m0 - mn0);
        const float alpha1 = __expf(m1 - mn1);

        float rs0 = 0.0f, rs1 = 0.0f;
#pragma unroll
        for (int nt = 0; nt < 8; nt++) {
            S[nt][0] = __expf(S[nt][0] - mn0);
            S[nt][1] = __expf(S[nt][1] - mn0);
            S[nt][2] = __expf(S[nt][2] - mn1);
            S[nt][3] = __expf(S[nt][3] - mn1);
            rs0 += S[nt][0] + S[nt][1];
            rs1 += S[nt][2] + S[nt][3];
        }
        rs0 += __shfl_xor_sync(0xffffffffu, rs0, 1);
        rs0 += __shfl_xor_sync(0xffffffffu, rs0, 2);
        rs1 += __shfl_xor_sync(0xffffffffu, rs1, 1);
        rs1 += __shfl_xor_sync(0xffffffffu, rs1, 2);

        l0 = l0 * alpha0 + rs0;  m0 = mn0;
        l1 = l1 * alpha1 + rs1;  m1 = mn1;

#pragma unroll
        for (int nt = 0; nt < 16; nt++) {
            O[nt][0] *= alpha0; O[nt][1] *= alpha0;
            O[nt][2] *= alpha1; O[nt][3] *= alpha1;
        }

        __syncthreads();   // all warps done reading K -> safe to overwrite as P

        // ---- write P (tf32) into KPs region, warp-private stripe ----
        uint32_t* Ps = KPs;
#pragma unroll
        for (int nt = 0; nt < 8; nt++) {
            const int cc = nt * 8 + 2 * qid;
            *(uint2*)(Ps + (row0 + grp) * PS_STR + cc) =
                make_uint2(f2tf32(S[nt][0]), f2tf32(S[nt][1]));
            *(uint2*)(Ps + (row0 + grp + 8) * PS_STR + cc) =
                make_uint2(f2tf32(S[nt][2]), f2tf32(S[nt][3]));
        }
        __syncwarp();

        // ---- O += P V : m16 x n128 x k64 per warp ----
#pragma unroll
        for (int ks = 0; ks < 8; ks++) {
            const int kk = ks * 8;
            uint32_t a0 = Ps[(row0 + grp) * PS_STR + kk + qid];
            uint32_t a1 = Ps[(row0 + grp + 8) * PS_STR + kk + qid];
            uint32_t a2 = Ps[(row0 + grp) * PS_STR + kk + qid + 4];
            uint32_t a3 = Ps[(row0 + grp + 8) * PS_STR + kk + qid + 4];
#pragma unroll
            for (int nt = 0; nt < 16; nt++) {
                uint32_t b0 = Vs[(kk + qid) * VS_STR + nt * 8 + grp];
                uint32_t b1 = Vs[(kk + qid + 4) * VS_STR + nt * 8 + grp];
                mma_tf32(O[nt][0], O[nt][1], O[nt][2], O[nt][3], a0, a1, a2, a3, b0, b1);
            }
        }
    }

    // Epilogue: normalize and store (c-frag layout)
    const float inv0 = 1.0f / l0;
    const float inv1 = 1.0f / l1;
    float* dst0 = out + (size_t)(q0 + row0 + grp) * D_MODEL + hq * HD;
    float* dst1 = out + (size_t)(q0 + row0 + grp + 8) * D_MODEL + hq * HD;
#pragma unroll
    for (int nt = 0; nt < 16; nt++) {
        const int cc = nt * 8 + 2 * qid;
        *(float2*)(dst0 + cc) = make_float2(O[nt][0] * inv0, O[nt][1] * inv0);
        *(float2*)(dst1 + cc) = make_float2(O[nt][2] * inv1, O[nt][3] * inv1);
    }
}

// ---------------------------------------------------------------------------
// Launch
// ---------------------------------------------------------------------------
extern "C" void kernel_launch(void* const* d_in, const int* in_sizes, int n_in,
                              void* d_out, int out_size)
{
    const float* x    = (const float*)d_in[0];  // (1, 2048, 2048)
    const float* Wqkv = (const float*)d_in[1];  // (2048, 3072)
    const float* Wo   = (const float*)d_in[2];  // (2048, 2048)
    const float* s    = (const float*)d_in[3];  // (1, 16)
    float* out = (float*)d_out;                 // (1, 2048, 2048)

    float* proj = nullptr;
    float* attn = nullptr;
    cudaGetSymbolAddress((void**)&proj, g_proj);
    cudaGetSymbolAddress((void**)&attn, g_attn);

    // 1) QKV projection: tf32 tensor cores
    {
        dim3 grid(QKV_DIM / 128, L_SEQ / 128);
        mma_gemm_kernel<<<grid, 256>>>(x, Wqkv, proj, L_SEQ, QKV_DIM, D_MODEL);
    }

    // 2) RoPE on q + k
    {
        dim3 grid(L_SEQ, NQH + NKVH);
        rope_kernel<<<grid, 64>>>(proj);
    }

    // 3) Fused attention: tf32 tensor cores
    {
        size_t smem = (size_t)(64 * QS_STR + 64 * KS_STR + 64 * VS_STR) * sizeof(uint32_t);
        cudaFuncSetAttribute(attn_mma_kernel, cudaFuncAttributeMaxDynamicSharedMemorySize, (int)smem);
        dim3 grid(L_SEQ / AT_BQ, NQH);
        attn_mma_kernel<<<grid, 128, smem>>>(proj, s, attn);
    }

    // 4) Output projection: tf32 tensor cores
    {
        dim3 grid(D_MODEL / 128, L_SEQ / 128);
        mma_gemm_kernel<<<grid, 256>>>(attn, Wo, out, L_SEQ, D_MODEL, D_MODEL);
    }
}